// round 7
// baseline (speedup 1.0000x reference)
#include <cuda_runtime.h>
#include <math.h>

#define Bb 64
#define Cc 8
#define Nn 2048
#define Tt 64
#define NSPLIT 8
#define BPG 8                               // batches per group: x[g] = 32 MB
#define GROUPS (Bb / BPG)                   // 8
#define RED_BLOCKS (BPG * Cc * NSPLIT)      // 512
#define AGG_BLOCKS (BPG * 128)              // 1024
#define ATT_BLOCKS BPG                      // 8
#define MAIN_BLOCKS (RED_BLOCKS + AGG_BLOCKS)   // 1536
#define ALL_BLOCKS (MAIN_BLOCKS + ATT_BLOCKS)   // 1544
#define NT4 (Nn * Tt / 4)                   // 32768 float4 per (b,c)

// scratch
__device__ float g_part[Bb * Cc * NSPLIT * Tt];   // reduction partials (1 MB)
__device__ float g_att[Bb * Cc * Cc];             // attention weights

union SmemU {
    struct { float alpha[256]; float4 red[256]; } r;
    struct { float W[64 * 64]; float k[8 * 64]; float m[8 * 64]; float sc[64]; } t;
    struct { float att[64]; } a;
};

// ---------------------------------------------------------------------------
// One pipeline step: reduce(red_g) || att(att_g) || agg(agg_g), independent.
//   bid in [0,1536): bid%3==2 -> reduce block (bid/3), else agg block
//   bid in [1536,1544): att block
// ---------------------------------------------------------------------------
__global__ void __launch_bounds__(256)
step_kernel(const float* __restrict__ x, const float* __restrict__ Wc,
            const float* __restrict__ alpha, float* __restrict__ out,
            int red_g, int att_g, int agg_g) {
    __shared__ SmemU S;
    int tid = threadIdx.x;
    int bid = blockIdx.x;

    if (bid >= MAIN_BLOCKS) {
        // ================= att path: 8 blocks, one per batch ===============
        if (att_g < 0) return;
        int b = att_g * BPG + (bid - MAIN_BLOCKS);
        if (tid < 64) {
            // warp-pair cooperative; use 64 of 256 threads
            for (int i = tid; i < 64 * 64; i += 64) S.t.W[i] = Wc[i];
            for (int i = tid; i < 8 * 64; i += 64) {
                int c = i >> 6, t = i & 63;
                const float* gp = g_part + ((long)(b * Cc + c) * NSPLIT) * Tt + t;
                float s = 0.f;
                #pragma unroll
                for (int p = 0; p < NSPLIT; p++) s += gp[p * Tt];
                S.t.k[i] = s;
            }
        }
        __syncthreads();
        if (tid < 64) {
            #pragma unroll
            for (int c = 0; c < 8; c++) {
                float acc = 0.f;
                #pragma unroll
                for (int t = 0; t < 64; t++) acc += S.t.k[c * 64 + t] * S.t.W[t * 64 + tid];
                S.t.m[c * 64 + tid] = acc;
            }
        }
        __syncthreads();
        if (tid < 64) {
            int c = tid >> 3, d = tid & 7;
            float sc = 0.f;
            #pragma unroll
            for (int s = 0; s < 64; s++) sc += S.t.m[c * 64 + s] * S.t.k[d * 64 + s];
            S.t.sc[tid] = sc;
        }
        __syncthreads();
        if (tid < 8) {
            float mx = -1e30f;
            #pragma unroll
            for (int j = 0; j < 8; j++) mx = fmaxf(mx, S.t.sc[tid * 8 + j]);
            float e[8], sum = 0.f;
            #pragma unroll
            for (int j = 0; j < 8; j++) { e[j] = __expf(S.t.sc[tid * 8 + j] - mx); sum += e[j]; }
            float inv = 1.f / sum;
            #pragma unroll
            for (int j = 0; j < 8; j++)
                g_att[b * Cc * Cc + tid * Cc + j] = e[j] * inv;
        }
        return;
    }

    int third = bid / 3;
    if (bid % 3 == 2) {
        // ================= reduce path: 512 blocks =========================
        if (red_g < 0) return;
        int r     = third;                  // 0..511
        int bcl   = r >> 3;
        int split = r & 7;
        int b     = red_g * BPG + (bcl >> 3);
        int c     = bcl & 7;
        const float* xp = x + ((long)(b * Cc + c)) * Nn * Tt;

        S.r.alpha[tid] = alpha[split * 256 + tid];
        __syncthreads();

        int t4 = tid & 15, row = tid >> 4;
        int nbase = split * 256;
        float4 acc = make_float4(0.f, 0.f, 0.f, 0.f);
        #pragma unroll
        for (int i = 0; i < 16; i++) {
            int nl = row + i * 16;
            float4 v = reinterpret_cast<const float4*>(xp + (long)(nbase + nl) * Tt)[t4];
            float a = S.r.alpha[nl];
            acc.x += v.x * a; acc.y += v.y * a;
            acc.z += v.z * a; acc.w += v.w * a;
        }

        S.r.red[tid] = acc;
        __syncthreads();
        #pragma unroll
        for (int off = 8; off >= 1; off >>= 1) {
            if (row < off) {
                float4 o = S.r.red[(row + off) * 16 + t4];
                acc.x += o.x; acc.y += o.y; acc.z += o.z; acc.w += o.w;
                S.r.red[tid] = acc;
            }
            __syncthreads();
        }
        if (row == 0)
            reinterpret_cast<float4*>(
                g_part + ((long)(b * Cc + c) * NSPLIT + split) * Tt)[t4] = acc;

    } else {
        // ================= agg path: 1024 blocks ===========================
        if (agg_g < 0) return;
        int aidx  = third * 2 + (bid % 3);  // 0..1023
        int bl    = aidx >> 7;              // 0..7
        int chunk = aidx & 127;
        int b     = agg_g * BPG + bl;

        if (tid < 64) S.a.att[tid] = g_att[b * 64 + tid];
        __syncthreads();

        int p = chunk * 256 + tid;
        const float4* xb = reinterpret_cast<const float4*>(x + (long)b * Cc * Nn * Tt);
        float4*       ob = reinterpret_cast<float4*>(out + (long)b * Cc * Nn * Tt);

        // prefetch all 8 channel vectors (MLP = 8); L2-resident, evict-first
        float4 v[8];
        #pragma unroll
        for (int i = 0; i < 8; i++)
            v[i] = __ldcs(&xb[(long)i * NT4 + p]);

        #pragma unroll
        for (int c = 0; c < 8; c++) {
            float4 acc = make_float4(0.f, 0.f, 0.f, 0.f);
            #pragma unroll
            for (int i = 0; i < 8; i++) {
                float a = S.a.att[c * 8 + i];
                acc.x += a * v[i].x; acc.y += a * v[i].y;
                acc.z += a * v[i].z; acc.w += a * v[i].w;
            }
            __stcs(&ob[(long)c * NT4 + p], acc);   // evict-first: protect x in L2
        }
    }
}

// ---------------------------------------------------------------------------
extern "C" void kernel_launch(void* const* d_in, const int* in_sizes, int n_in,
                              void* d_out, int out_size) {
    const float* x     = (const float*)d_in[0];
    const float* Wc    = (const float*)d_in[1];
    const float* alpha = (const float*)d_in[2];
    float* out = (float*)d_out;

    // depth-2 pipeline: step s = reduce(s) || att(s-1) || agg(s-2)
    for (int s = 0; s < GROUPS + 2; s++) {
        int red_g = (s < GROUPS) ? s : -1;
        int att_g = (s - 1 >= 0 && s - 1 < GROUPS) ? s - 1 : -1;
        int agg_g = (s - 2 >= 0) ? s - 2 : -1;
        step_kernel<<<ALL_BLOCKS, 256>>>(x, Wc, alpha, out, red_g, att_g, agg_g);
    }
}

// round 8
// speedup vs baseline: 1.4814x; 1.4814x over previous
#include <cuda_runtime.h>
#include <math.h>

#define Bb 64
#define Cc 8
#define Nn 2048
#define Tt 64
#define NSPLIT 4
#define NROWS (Nn / NSPLIT)                 // 512 rows per reduce block
#define RED_BLOCKS (Bb * Cc * NSPLIT)       // 2048
#define AGG_BLOCKS (Bb * 128)               // 8192
#define NT4 (Nn * Tt / 4)                   // 32768 float4 per (b,c)

// scratch
__device__ float g_part[Bb * Cc * NSPLIT * Tt];   // reduction partials (512 KB)
__device__ float g_att[Bb * Cc * Cc];             // attention weights

// ---------------------------------------------------------------------------
// Kernel 1: partial k. Block = (b, c, split); 256 threads = 16 rows x 16 lanes.
// Each row-thread accumulates 32 n-rows -> smem tree -> g_part.
// ---------------------------------------------------------------------------
__global__ void __launch_bounds__(256)
k_reduce(const float* __restrict__ x, const float* __restrict__ alpha) {
    int r     = blockIdx.x;
    int split = r & (NSPLIT - 1);
    int bc    = r >> 2;                      // b*Cc + c
    const float* xp = x + (long)bc * Nn * Tt + (long)split * NROWS * Tt;

    __shared__ float s_alpha[NROWS];         // 2 KB
    __shared__ float4 s_red[256];            // 4 KB

    int tid = threadIdx.x;
    for (int i = tid; i < NROWS; i += 256) s_alpha[i] = alpha[split * NROWS + i];
    __syncthreads();

    int t4 = tid & 15, row = tid >> 4;
    float4 acc = make_float4(0.f, 0.f, 0.f, 0.f);
    #pragma unroll 8
    for (int i = 0; i < NROWS / 16; i++) {   // 32 iters
        int nl = row + i * 16;
        float4 v = __ldcs(&reinterpret_cast<const float4*>(xp + (long)nl * Tt)[t4]);
        float a = s_alpha[nl];
        acc.x += v.x * a; acc.y += v.y * a;
        acc.z += v.z * a; acc.w += v.w * a;
    }

    s_red[tid] = acc;
    __syncthreads();
    #pragma unroll
    for (int off = 8; off >= 1; off >>= 1) {
        if (row < off) {
            float4 o = s_red[(row + off) * 16 + t4];
            acc.x += o.x; acc.y += o.y; acc.z += o.z; acc.w += o.w;
            s_red[tid] = acc;
        }
        __syncthreads();
    }
    if (row == 0)
        reinterpret_cast<float4*>(
            g_part + ((long)bc * NSPLIT + split) * Tt)[t4] = acc;
}

// ---------------------------------------------------------------------------
// Kernel 2: att[b] per block. 64 blocks x 64 threads.
// ---------------------------------------------------------------------------
__global__ void __launch_bounds__(64)
k_att(const float* __restrict__ Wc) {
    int b = blockIdx.x;
    int tid = threadIdx.x;                   // 0..63

    __shared__ float sW[64 * 64];
    __shared__ float sk[8 * 64];
    __shared__ float sm[8 * 64];
    __shared__ float ssc[64];

    for (int i = tid; i < 64 * 64; i += 64) sW[i] = Wc[i];
    for (int i = tid; i < 8 * 64; i += 64) {
        int c = i >> 6, t = i & 63;
        const float* gp = g_part + ((long)(b * Cc + c) * NSPLIT) * Tt + t;
        float s = 0.f;
        #pragma unroll
        for (int p = 0; p < NSPLIT; p++) s += gp[p * Tt];
        sk[i] = s;
    }
    __syncthreads();

    #pragma unroll
    for (int c = 0; c < 8; c++) {
        float acc = 0.f;
        #pragma unroll
        for (int t = 0; t < 64; t++) acc += sk[c * 64 + t] * sW[t * 64 + tid];
        sm[c * 64 + tid] = acc;
    }
    __syncthreads();

    int c = tid >> 3, d = tid & 7;
    float sc = 0.f;
    #pragma unroll
    for (int s = 0; s < 64; s++) sc += sm[c * 64 + s] * sk[d * 64 + s];
    ssc[tid] = sc;
    __syncthreads();

    if (tid < 8) {
        float mx = -1e30f;
        #pragma unroll
        for (int j = 0; j < 8; j++) mx = fmaxf(mx, ssc[tid * 8 + j]);
        float e[8], sum = 0.f;
        #pragma unroll
        for (int j = 0; j < 8; j++) { e[j] = __expf(ssc[tid * 8 + j] - mx); sum += e[j]; }
        float inv = 1.f / sum;
        #pragma unroll
        for (int j = 0; j < 8; j++)
            g_att[b * Cc * Cc + tid * Cc + j] = e[j] * inv;
    }
}

// ---------------------------------------------------------------------------
// Kernel 3: out[b,c,n,t] = sum_i att[b,c,i] * x[b,i,n,t]
// 8192 blocks x 256 threads; MLP-8 prefetch; ldcs/stcs streaming hints.
// ---------------------------------------------------------------------------
__global__ void __launch_bounds__(256)
k_agg(const float* __restrict__ x, float* __restrict__ out) {
    int b     = blockIdx.x >> 7;             // 128 blocks per batch
    int chunk = blockIdx.x & 127;
    int tid   = threadIdx.x;

    __shared__ float satt[64];
    if (tid < 64) satt[tid] = g_att[b * 64 + tid];
    __syncthreads();

    int p = chunk * 256 + tid;
    const float4* xb = reinterpret_cast<const float4*>(x + (long)b * Cc * Nn * Tt);
    float4*       ob = reinterpret_cast<float4*>(out + (long)b * Cc * Nn * Tt);

    // prefetch all 8 channel vectors (MLP = 8); x dead after this -> evict-first
    float4 v[8];
    #pragma unroll
    for (int i = 0; i < 8; i++)
        v[i] = __ldcs(&xb[(long)i * NT4 + p]);

    #pragma unroll
    for (int c = 0; c < 8; c++) {
        float4 acc = make_float4(0.f, 0.f, 0.f, 0.f);
        #pragma unroll
        for (int i = 0; i < 8; i++) {
            float a = satt[c * 8 + i];
            acc.x += a * v[i].x; acc.y += a * v[i].y;
            acc.z += a * v[i].z; acc.w += a * v[i].w;
        }
        __stcs(&ob[(long)c * NT4 + p], acc);
    }
}

// ---------------------------------------------------------------------------
extern "C" void kernel_launch(void* const* d_in, const int* in_sizes, int n_in,
                              void* d_out, int out_size) {
    const float* x     = (const float*)d_in[0];
    const float* Wc    = (const float*)d_in[1];
    const float* alpha = (const float*)d_in[2];
    float* out = (float*)d_out;

    k_reduce<<<RED_BLOCKS, 256>>>(x, alpha);
    k_att<<<Bb, 64>>>(Wc);
    k_agg<<<AGG_BLOCKS, 256>>>(x, out);
}